// round 16
// baseline (speedup 1.0000x reference)
#include <cuda_runtime.h>
#include <math_constants.h>

#define N_IN   16384
#define NCONV  128
#define KMAX   11
#define TPB    256
#define CPB    16    // convs per block (processed block-cooperatively)
#define CHUNK  65    // 65 == 1 (mod 32) -> conflict-free lanes for any dilation
#define NWARP  (TPB / 32)

__device__ __forceinline__ float warpReduceMax(float v) {
#pragma unroll
    for (int o = 16; o > 0; o >>= 1)
        v = fmaxf(v, __shfl_xor_sync(0xffffffffu, v, o));
    return v;
}
__device__ __forceinline__ int warpReduceSum(int v) {
#pragma unroll
    for (int o = 16; o > 0; o >>= 1)
        v += __shfl_xor_sync(0xffffffffu, v, o);
    return v;
}

__device__ __forceinline__ int meta_at(const void* arr, int c, bool is64) {
    if (is64) return (int)((const long long*)arr)[c];
    return ((const int*)arr)[c];
}

// ---- ring FIR, no bounds checks. Loads exactly len+K-1 taps:
// preload K-1, then load-one/compute-one. Max address: i0+(len+K-2)*d. ----
template <int K>
__device__ __forceinline__ void ring_fast(
    const float* __restrict__ xs, const float* __restrict__ w, float bias,
    int i0, int d, int len, float& mx, int& neg)
{
    const float* ptr = xs + i0;
    float z[K];
#pragma unroll
    for (int s = 0; s < K - 1; s++) { z[s] = *ptr; ptr += d; }

    const int full = len / K;
    const int rem  = len - full * K;

    for (int g = 0; g < full; g++) {
#pragma unroll
        for (int s = 0; s < K; s++) {
            z[(s + K - 1) % K] = *ptr; ptr += d;   // newest tap
            float y = fmaf(w[0], z[s % K], bias);
#pragma unroll
            for (int t = 1; t < K; t++)
                y = fmaf(w[t], z[(s + t) % K], y);
            mx = fmaxf(mx, y);
            neg += (int)(__float_as_uint(y) >> 31);
        }
    }
    if (rem) {
#pragma unroll
        for (int s = 0; s < K; s++) {
            if (s < rem) {
                z[(s + K - 1) % K] = *ptr; ptr += d;
                float y = fmaf(w[0], z[s % K], bias);
#pragma unroll
                for (int t = 1; t < K; t++)
                    y = fmaf(w[t], z[(s + t) % K], y);
                mx = fmaxf(mx, y);
                neg += (int)(__float_as_uint(y) >> 31);
            }
        }
    }
}

// ---- same ring, OOB taps clamped to zero sentinel xs[N_IN] (edge chunks) ----
template <int K>
__device__ __forceinline__ void ring_clamped(
    const float* __restrict__ xs, const float* __restrict__ w, float bias,
    int i0, int d, int len, float& mx, int& neg)
{
    int ix = i0;
    float z[K];
#pragma unroll
    for (int s = 0; s < K - 1; s++) {
        unsigned ui = min((unsigned)ix, (unsigned)N_IN);
        z[s] = xs[ui]; ix += d;
    }

    const int full = len / K;
    const int rem  = len - full * K;

    for (int g = 0; g < full; g++) {
#pragma unroll
        for (int s = 0; s < K; s++) {
            unsigned ui = min((unsigned)ix, (unsigned)N_IN);
            z[(s + K - 1) % K] = xs[ui]; ix += d;
            float y = fmaf(w[0], z[s % K], bias);
#pragma unroll
            for (int t = 1; t < K; t++)
                y = fmaf(w[t], z[(s + t) % K], y);
            mx = fmaxf(mx, y);
            neg += (int)(__float_as_uint(y) >> 31);
        }
    }
    if (rem) {
#pragma unroll
        for (int s = 0; s < K; s++) {
            if (s < rem) {
                unsigned ui = min((unsigned)ix, (unsigned)N_IN);
                z[(s + K - 1) % K] = xs[ui]; ix += d;
                float y = fmaf(w[0], z[s % K], bias);
#pragma unroll
                for (int t = 1; t < K; t++)
                    y = fmaf(w[t], z[(s + t) % K], y);
                mx = fmaxf(mx, y);
                neg += (int)(__float_as_uint(y) >> 31);
            }
        }
    }
}

template <int K>
__device__ __forceinline__ void conv_feat_dec(
    const float* __restrict__ xs,
    const float* __restrict__ wrow, float bias,
    int d, int p, int L,
    float& mx_out, int& neg_out)
{
    float w[K];
#pragma unroll
    for (int j = 0; j < K; j++) w[j] = wrow[j];

    float mx = -CUDART_INF_F;
    int   neg = 0;

    // Per-conv division results (2 divides total, amortized over all items):
    //   floor((p+r)/d) = pq + (prm + r >= d)   for r in [0,d)
    //   floor((A-r)/d) = aq  - (r > arm)       for r in [0,d), A >= 0
    const int A   = L - 1 - p;
    const int pq  = p / d, prm = p - pq * d;
    const int aq  = A / d, arm = A - aq * d;

    if (d >= TPB) {
        // one item per phase; full phase in one chunk
        for (int r = threadIdx.x; r < d; r += TPB) {
            const int m_lo = -(pq + ((prm + r) >= d ? 1 : 0));
            const int m_hi = aq - (r > arm ? 1 : 0);
            const int len  = m_hi - m_lo + 1;
            if (len <= 0) continue;
            const int i0 = r + m_lo * d;
            if (i0 >= 0 && i0 + (len + K - 2) * d < N_IN)
                ring_fast<K>(xs, w, bias, i0, d, len, mx, neg);
            else
                ring_clamped<K>(xs, w, bias, i0, d, len, mx, neg);
        }
    } else {
        const int maxlen = (L + d - 1) / d;
        const int nQ     = (maxlen + CHUNK - 1) / CHUNK;
        const int nItems = d * nQ;
        const float rd   = 1.0f / (float)d;

        for (int j = threadIdx.x; j < nItems; j += TPB) {
            // q = j / d, r = j % d via float reciprocal (+/-1 fixup)
            int q = (int)((float)j * rd);
            int r = j - q * d;
            if (r < 0)       { r += d; q--; }
            else if (r >= d) { r -= d; q++; }

            const int m_lo = -(pq + ((prm + r) >= d ? 1 : 0));
            const int m_hi = aq - (r > arm ? 1 : 0);
            const int m0   = m_lo + q * CHUNK;
            const int m1   = min(m0 + CHUNK, m_hi + 1);
            const int len  = m1 - m0;
            if (len <= 0) continue;
            const int i0 = r + m0 * d;
            if (i0 >= 0 && i0 + (len + K - 2) * d < N_IN)
                ring_fast<K>(xs, w, bias, i0, d, len, mx, neg);
            else
                ring_clamped<K>(xs, w, bias, i0, d, len, mx, neg);
        }
    }

    mx_out = mx;
    neg_out = neg;
}

__global__ void __launch_bounds__(TPB)
feat_kernel(const float* __restrict__ x,
            const float* __restrict__ W,
            const float* __restrict__ B,
            const void* __restrict__ KS,
            const void* __restrict__ DS,
            const void* __restrict__ PS,
            float* __restrict__ out)
{
    extern __shared__ float xs[];   // N_IN + zero sentinel
    const int b = blockIdx.y;

    {
        const float4* xr4 = (const float4*)(x + (size_t)b * N_IN);
        float4* xs4 = (float4*)xs;
        for (int i = threadIdx.x; i < N_IN / 4; i += TPB)
            xs4[i] = xr4[i];
        if (threadIdx.x == 0) xs[N_IN] = 0.0f;
    }

    // per-(conv, warp) partials: written without any inter-conv barriers
    __shared__ float rmax[CPB][NWARP];
    __shared__ int   rneg[CPB][NWARP];
    __syncthreads();

    // int64 vs int32 metadata: kernel_sizes[0] in {7,9,11}; for int64 the
    // second 32-bit word is 0, for int32 it's kernel_sizes[1] (>=7).
    const bool is64 = (((const int*)KS)[1] == 0);

    const int warp = threadIdx.x >> 5;
    const int lane = threadIdx.x & 31;
    const int c0 = blockIdx.x * CPB;

    // No barriers inside this loop: warps drift through convs independently,
    // pooling per-conv imbalance across all CPB convs.
    for (int ci = 0; ci < CPB; ++ci) {
        const int c = c0 + ci;
        const int k = meta_at(KS, c, is64);
        const int d = meta_at(DS, c, is64);
        const int p = meta_at(PS, c, is64);
        const int L = N_IN + 2 * p - d * (k - 1);

        const float* wrow = W + c * KMAX;
        const float bias  = B[c];

        float mx; int neg;
        if (k == 7)       conv_feat_dec<7 >(xs, wrow, bias, d, p, L, mx, neg);
        else if (k == 9)  conv_feat_dec<9 >(xs, wrow, bias, d, p, L, mx, neg);
        else              conv_feat_dec<11>(xs, wrow, bias, d, p, L, mx, neg);

        mx  = warpReduceMax(mx);     // shfl-based: no block barrier needed
        neg = warpReduceSum(neg);
        if (lane == 0) { rmax[ci][warp] = mx; rneg[ci][warp] = neg; }
    }

    __syncthreads();   // single barrier: all partials visible

    // final reduce: one thread per conv (threads 0..CPB-1)
    if (threadIdx.x < CPB) {
        const int ci = threadIdx.x;
        const int c  = c0 + ci;
        const int k = meta_at(KS, c, is64);
        const int d = meta_at(DS, c, is64);
        const int p = meta_at(PS, c, is64);
        const int L = N_IN + 2 * p - d * (k - 1);

        float m = rmax[ci][0];
        int   n = rneg[ci][0];
#pragma unroll
        for (int i = 1; i < NWARP; i++) {
            m = fmaxf(m, rmax[ci][i]);
            n += rneg[ci][i];
        }
        const size_t base = (size_t)b * (2 * NCONV) + 2 * c;
        out[base]     = m;
        out[base + 1] = (float)(L - n) / (float)L;
    }
}

extern "C" void kernel_launch(void* const* d_in, const int* in_sizes, int n_in,
                              void* d_out, int out_size)
{
    const float* x  = (const float*)d_in[0];
    const float* W  = (const float*)d_in[1];
    const float* B  = (const float*)d_in[2];
    const void*  KS = d_in[3];
    const void*  DS = d_in[4];
    const void*  PS = d_in[5];
    float* out = (float*)d_out;

    const int batch = in_sizes[0] / N_IN;   // 256

    const size_t smem = (N_IN + 16) * sizeof(float);
    cudaFuncSetAttribute(feat_kernel,
                         cudaFuncAttributeMaxDynamicSharedMemorySize,
                         (int)smem);

    dim3 grid(NCONV / CPB, batch);
    feat_kernel<<<grid, TPB, smem>>>(x, W, B, KS, DS, PS, out);
}